// round 2
// baseline (speedup 1.0000x reference)
#include <cuda_runtime.h>
#include <cuda_fp16.h>
#include <cstdint>

// Problem dims (fixed per reference)
#define DIM_M 512
#define DIM_K 4096
#define DIM_N 11008

#define CTA_M 128
#define CTA_N 128
#define KSTEP 64                 // halves per K step
#define ITERS (DIM_K / KSTEP)    // 64
#define GRID_MT (DIM_M / CTA_M)  // 4
#define GRID_NT (DIM_N / CTA_N)  // 86

// SMEM: rows padded to 144B so 8-row ldmatrix bases are all distinct mod 128 (conflict-free)
#define ROWB 144
#define TILE_BYTES (128 * ROWB)          // 18432
#define STAGE_BYTES (2 * TILE_BYTES)     // A + B per stage
#define SMEM_TOTAL (2 * STAGE_BYTES)     // 73728

// x converted to fp16, row-major [512][4096]
__device__ __align__(16) __half g_x16[DIM_M * DIM_K];

__device__ __forceinline__ uint32_t smem_u32(const void* p) {
    uint32_t a;
    asm("{ .reg .u64 t; cvta.to.shared.u64 t, %1; cvt.u32.u64 %0, t; }" : "=r"(a) : "l"(p));
    return a;
}

__device__ __forceinline__ void cp_async16(uint32_t dst, const void* src) {
    asm volatile("cp.async.cg.shared.global [%0], [%1], 16;" :: "r"(dst), "l"(src));
}
__device__ __forceinline__ void cp_commit() { asm volatile("cp.async.commit_group;"); }
__device__ __forceinline__ void cp_wait0()  { asm volatile("cp.async.wait_group 0;"); }

__device__ __forceinline__ void ldsm4(uint32_t* r, uint32_t addr) {
    asm volatile("ldmatrix.sync.aligned.m8n8.x4.shared.b16 {%0,%1,%2,%3}, [%4];"
                 : "=r"(r[0]), "=r"(r[1]), "=r"(r[2]), "=r"(r[3]) : "r"(addr));
}

__device__ __forceinline__ void mma16816(float* d, const uint32_t* a, const uint32_t* b) {
    asm volatile(
        "mma.sync.aligned.m16n8k16.row.col.f32.f16.f16.f32 "
        "{%0,%1,%2,%3}, {%4,%5,%6,%7}, {%8,%9}, {%0,%1,%2,%3};"
        : "+f"(d[0]), "+f"(d[1]), "+f"(d[2]), "+f"(d[3])
        : "r"(a[0]), "r"(a[1]), "r"(a[2]), "r"(a[3]), "r"(b[0]), "r"(b[1]));
}

__device__ __forceinline__ uint32_t pack2(float a, float b) {
    __half2 h = __floats2half2_rn(a, b);
    return *reinterpret_cast<uint32_t*>(&h);
}

// ---------------- kernel 0: x fp32 -> fp16 row-major ----------------
__global__ void __launch_bounds__(256) convert_x_kernel(const float* __restrict__ x) {
    int gid = blockIdx.x * blockDim.x + threadIdx.x;   // 262144 threads * 8 elems
    const float4* src = reinterpret_cast<const float4*>(x) + gid * 2;
    float4 f0 = __ldg(src);
    float4 f1 = __ldg(src + 1);
    uint4 v;
    v.x = pack2(f0.x, f0.y);
    v.y = pack2(f0.z, f0.w);
    v.z = pack2(f1.x, f1.y);
    v.w = pack2(f1.z, f1.w);
    reinterpret_cast<uint4*>(g_x16)[gid] = v;
}

// ---------------- kernel 1: fused dequant + HMMA GEMM ----------------
__global__ void __launch_bounds__(256, 1) gemm_kernel(const int* __restrict__ w,
                                                      const float* __restrict__ saz,
                                                      float* __restrict__ out) {
    extern __shared__ __align__(1024) char smem[];
    const uint32_t sb = smem_u32(smem);
    const int tid = threadIdx.x;
    const int wid = tid >> 5;
    const int lid = tid & 31;

    // m-fast grid ordering: CTAs sharing a weight N-tile are adjacent -> L2 reuse
    const int mtile = blockIdx.x & 3;
    const int ntile = blockIdx.x >> 2;
    const int mbase = mtile * CTA_M;
    const int nbase = ntile * CTA_N;

    const int warp_m = wid & 1;           // 2 warps along M
    const int warp_n = wid >> 1;          // 4 warps along N
    const int m0w = warp_m * 64;
    const int n0w = warp_n * 32;

    // ---- global load assignments ----
    const int r = tid >> 1;               // 0..127 (row within tile, both A and B)
    const int hf = tid & 1;               // which 32-half of the K step
    const __half* a_src = g_x16 + (size_t)(mbase + r) * DIM_K + hf * 32;       // + ks*64
    const int4* b_src = reinterpret_cast<const int4*>(w + (size_t)(nbase + r) * DIM_K + hf * 32); // + ks*16
    const float2* sz_src = reinterpret_cast<const float2*>(saz) + (nbase + r); // + g*DIM_N

    // ---- ldmatrix address bases (per-thread, per-stage add later) ----
    // A: rows = m (lanes 0-15 rows, 16-31 repeat), col halves: lanes>=16 get +8 cols
    const uint32_t a_lane_off = (uint32_t)(m0w + (lid & 15)) * ROWB + ((lid >> 4) << 4);
    // B: rows = n, m0/m1 = low/high k chunk, m2/m3 = rows +8
    const uint32_t b_lane_off = (uint32_t)(n0w + (lid & 7) + ((lid >> 4) & 1) * 8) * ROWB
                                + (((lid >> 3) & 1) << 4);

    float d[4][4][4];
    #pragma unroll
    for (int i = 0; i < 4; ++i)
        #pragma unroll
        for (int j = 0; j < 4; ++j)
            #pragma unroll
            for (int k = 0; k < 4; ++k) d[i][j][k] = 0.f;

    int4 br[8];
    float2 sz;

    // ---- helpers as macros over locals ----
    #define ISSUE_A(ks, stg) do {                                                   \
        uint32_t dstA = sb + (stg) * STAGE_BYTES + (uint32_t)r * ROWB + (hf ? 64u : 0u); \
        const __half* sA = a_src + (ks) * KSTEP;                                    \
        _Pragma("unroll")                                                           \
        for (int j = 0; j < 4; ++j) cp_async16(dstA + j * 16, sA + j * 8);          \
        cp_commit();                                                                \
    } while (0)

    #define LOAD_B(ks) do {                                                         \
        const int4* sB = b_src + (ks) * 16;                                         \
        _Pragma("unroll")                                                           \
        for (int j = 0; j < 8; ++j) br[j] = __ldg(&sB[j]);                          \
        sz = __ldg(sz_src + ((ks) >> 1) * DIM_N);                                   \
    } while (0)

    #define STS_B(stg) do {                                                         \
        char* dstB = smem + (stg) * STAGE_BYTES + TILE_BYTES + r * ROWB + hf * 64;  \
        const float s = sz.x, z = sz.y;                                             \
        _Pragma("unroll")                                                           \
        for (int j = 0; j < 4; ++j) {                                               \
            int4 p = br[2 * j], q = br[2 * j + 1];                                  \
            uint4 v;                                                                \
            v.x = pack2((float)(p.x - 8) * s + z, (float)(p.y - 8) * s + z);        \
            v.y = pack2((float)(p.z - 8) * s + z, (float)(p.w - 8) * s + z);        \
            v.z = pack2((float)(q.x - 8) * s + z, (float)(q.y - 8) * s + z);        \
            v.w = pack2((float)(q.z - 8) * s + z, (float)(q.w - 8) * s + z);        \
            *reinterpret_cast<uint4*>(dstB + j * 16) = v;                           \
        }                                                                           \
    } while (0)

    // ---- prologue: stage 0 ----
    ISSUE_A(0, 0);
    LOAD_B(0);
    STS_B(0);
    cp_wait0();
    __syncthreads();

    for (int ks = 0; ks < ITERS; ++ks) {
        const int cur = ks & 1;
        const int nxt = cur ^ 1;
        if (ks < ITERS - 1) {
            ISSUE_A(ks + 1, nxt);
            LOAD_B(ks + 1);
        }

        // ---- compute on cur stage ----
        const uint32_t aBase = sb + cur * STAGE_BYTES + a_lane_off;
        const uint32_t bBase = sb + cur * STAGE_BYTES + TILE_BYTES + b_lane_off;
        #pragma unroll
        for (int kc = 0; kc < 4; ++kc) {
            uint32_t a[4][4];
            uint32_t b[4][2];
            #pragma unroll
            for (int mt = 0; mt < 4; ++mt)
                ldsm4(a[mt], aBase + (uint32_t)mt * (16 * ROWB) + kc * 32);
            #pragma unroll
            for (int nt = 0; nt < 2; ++nt) {
                uint32_t t[4];
                ldsm4(t, bBase + (uint32_t)nt * (16 * ROWB) + kc * 32);
                b[2 * nt][0] = t[0]; b[2 * nt][1] = t[1];
                b[2 * nt + 1][0] = t[2]; b[2 * nt + 1][1] = t[3];
            }
            #pragma unroll
            for (int mt = 0; mt < 4; ++mt)
                #pragma unroll
                for (int n8 = 0; n8 < 4; ++n8)
                    mma16816(d[mt][n8], a[mt], b[n8]);
        }

        if (ks < ITERS - 1) {
            STS_B(nxt);
            cp_wait0();
        }
        __syncthreads();
    }

    // ---- epilogue: registers -> gmem fp32 ----
    const int g = lid >> 2;
    const int tc = (lid & 3) * 2;
    #pragma unroll
    for (int mt = 0; mt < 4; ++mt) {
        const int row0 = mbase + m0w + mt * 16 + g;
        #pragma unroll
        for (int n8 = 0; n8 < 4; ++n8) {
            const int col = nbase + n0w + n8 * 8 + tc;
            float2 lo, hi;
            lo.x = d[mt][n8][0]; lo.y = d[mt][n8][1];
            hi.x = d[mt][n8][2]; hi.y = d[mt][n8][3];
            *reinterpret_cast<float2*>(out + (size_t)row0 * DIM_N + col) = lo;
            *reinterpret_cast<float2*>(out + (size_t)(row0 + 8) * DIM_N + col) = hi;
        }
    }
}

extern "C" void kernel_launch(void* const* d_in, const int* in_sizes, int n_in,
                              void* d_out, int out_size) {
    const float* x   = (const float*)d_in[0];
    const int*   w   = (const int*)d_in[1];
    const float* saz = (const float*)d_in[2];
    float* out = (float*)d_out;

    cudaFuncSetAttribute(gemm_kernel, cudaFuncAttributeMaxDynamicSharedMemorySize, SMEM_TOTAL);

    convert_x_kernel<<<(DIM_M * DIM_K / 8) / 256, 256>>>(x);
    gemm_kernel<<<GRID_MT * GRID_NT, 256, SMEM_TOTAL>>>(w, saz, out);
}

// round 5
// speedup vs baseline: 2.0857x; 2.0857x over previous
#include <cuda_runtime.h>
#include <cuda_fp16.h>
#include <cstdint>

// Problem dims (fixed per reference)
#define DIM_M 512
#define DIM_K 4096
#define DIM_N 11008

#define CTA_M 128
#define CTA_N 128
#define KSTEP 64                 // halves per K step
#define ITERS (DIM_K / KSTEP)    // 64
#define STAGES 3
#define GRID_MT (DIM_M / CTA_M)  // 4
#define GRID_NT (DIM_N / CTA_N)  // 86

// SMEM rows padded to 144B -> 8-row ldmatrix bases distinct mod 128 (conflict-free)
#define ROWB 144
#define TILE_BYTES (128 * ROWB)          // 18432
#define STAGE_BYTES (2 * TILE_BYTES)     // A + B per stage = 36864
#define SMEM_TOTAL (STAGES * STAGE_BYTES) // 110592

// x converted to fp16, row-major [512][4096]
__device__ __align__(16) __half g_x16[DIM_M * DIM_K];
// weights dequantized to fp16, row-major [11008][4096]
__device__ __align__(16) __half g_w16[(size_t)DIM_N * DIM_K];

__device__ __forceinline__ uint32_t smem_u32(const void* p) {
    uint32_t a;
    asm("{ .reg .u64 t; cvta.to.shared.u64 t, %1; cvt.u32.u64 %0, t; }" : "=r"(a) : "l"(p));
    return a;
}

__device__ __forceinline__ void cp_async16(uint32_t dst, const void* src) {
    asm volatile("cp.async.cg.shared.global [%0], [%1], 16;" :: "r"(dst), "l"(src));
}
__device__ __forceinline__ void cp_commit() { asm volatile("cp.async.commit_group;"); }

__device__ __forceinline__ void ldsm4(uint32_t* r, uint32_t addr) {
    asm volatile("ldmatrix.sync.aligned.m8n8.x4.shared.b16 {%0,%1,%2,%3}, [%4];"
                 : "=r"(r[0]), "=r"(r[1]), "=r"(r[2]), "=r"(r[3]) : "r"(addr));
}

__device__ __forceinline__ void mma16816(float* d, const uint32_t* a, const uint32_t* b) {
    asm volatile(
        "mma.sync.aligned.m16n8k16.row.col.f32.f16.f16.f32 "
        "{%0,%1,%2,%3}, {%4,%5,%6,%7}, {%8,%9}, {%0,%1,%2,%3};"
        : "+f"(d[0]), "+f"(d[1]), "+f"(d[2]), "+f"(d[3])
        : "r"(a[0]), "r"(a[1]), "r"(a[2]), "r"(a[3]), "r"(b[0]), "r"(b[1]));
}

__device__ __forceinline__ uint32_t pack2(float a, float b) {
    __half2 h = __floats2half2_rn(a, b);
    return *reinterpret_cast<uint32_t*>(&h);
}

// ---------------- kernel 0: x fp32 -> fp16 row-major ----------------
__global__ void __launch_bounds__(256) convert_x_kernel(const float* __restrict__ x) {
    int gid = blockIdx.x * blockDim.x + threadIdx.x;
    const float4* src = reinterpret_cast<const float4*>(x) + gid * 2;
    float4 f0 = __ldg(src);
    float4 f1 = __ldg(src + 1);
    uint4 v;
    v.x = pack2(f0.x, f0.y);
    v.y = pack2(f0.z, f0.w);
    v.z = pack2(f1.x, f1.y);
    v.w = pack2(f1.z, f1.w);
    reinterpret_cast<uint4*>(g_x16)[gid] = v;
}

// ---------------- kernel 1: dequant weights int32(4bit codes) -> fp16 ----------------
__global__ void __launch_bounds__(256) dequant_w_kernel(const int* __restrict__ w,
                                                        const float* __restrict__ saz) {
    int gid = blockIdx.x * blockDim.x + threadIdx.x;   // N*K/8 threads
    int n = gid >> 9;                // DIM_K/8 = 512 chunks per row
    int kc = (gid & 511) << 3;
    int g = kc >> 7;                 // group of 128
    float2 sz = __ldg(reinterpret_cast<const float2*>(saz) + (size_t)g * DIM_N + n);
    const float s = sz.x, z = sz.y;
    const int4* src = reinterpret_cast<const int4*>(w + (size_t)n * DIM_K + kc);
    int4 a = __ldg(src);
    int4 b = __ldg(src + 1);
    uint4 v;
    v.x = pack2((float)(a.x - 8) * s + z, (float)(a.y - 8) * s + z);
    v.y = pack2((float)(a.z - 8) * s + z, (float)(a.w - 8) * s + z);
    v.z = pack2((float)(b.x - 8) * s + z, (float)(b.y - 8) * s + z);
    v.w = pack2((float)(b.z - 8) * s + z, (float)(b.w - 8) * s + z);
    reinterpret_cast<uint4*>(g_w16)[gid] = v;
}

// ---------------- kernel 2: fp16 HMMA GEMM, 3-stage cp.async pipeline ----------------
__global__ void __launch_bounds__(512, 1) gemm_kernel(float* __restrict__ out) {
    extern __shared__ __align__(1024) char smem[];
    const uint32_t sb = smem_u32(smem);
    const int tid = threadIdx.x;
    const int wid = tid >> 5;
    const int lid = tid & 31;

    // m-fast grid ordering: 4 CTAs sharing a weight N-tile run concurrently -> L2 reuse
    const int mtile = blockIdx.x & 3;
    const int ntile = blockIdx.x >> 2;
    const int mbase = mtile * CTA_M;
    const int nbase = ntile * CTA_N;

    // 4x4 warp grid, warp tile 32x32
    const int m0w = (wid & 3) * 32;
    const int n0w = (wid >> 2) * 32;

    // ---- cp.async assignment: full tile coverage ----
    // tile = 128 rows x 8 chunks(16B). 512 threads x 2 chunks each per operand.
    // thread covers rows r0 and r0+64, chunk c.
    const int r0 = tid >> 3;         // 0..63
    const int c  = tid & 7;          // 0..7
    const __half* aG = g_x16 + (size_t)(mbase + r0) * DIM_K + c * 8;
    const __half* bG = g_w16 + (size_t)(nbase + r0) * DIM_K + c * 8;
    const uint32_t stg_off = (uint32_t)r0 * ROWB + c * 16;
    const size_t gstep = (size_t)64 * DIM_K;        // +64 rows in gmem
    const uint32_t sstep = 64u * ROWB;              // +64 rows in smem

    // ---- ldmatrix lane bases ----
    const uint32_t a_lane_off = (uint32_t)(m0w + (lid & 15)) * ROWB + ((lid >> 4) << 4);
    const uint32_t b_lane_off = (uint32_t)(n0w + (lid & 7) + ((lid >> 4) & 1) * 8) * ROWB
                                + (((lid >> 3) & 1) << 4);

    float d[2][4][4];
    #pragma unroll
    for (int i = 0; i < 2; ++i)
        #pragma unroll
        for (int j = 0; j < 4; ++j)
            #pragma unroll
            for (int k = 0; k < 4; ++k) d[i][j][k] = 0.f;

    #define ISSUE_STAGE(ks, buf) do {                                     \
        const uint32_t st = sb + (buf) * STAGE_BYTES + stg_off;           \
        const __half* sa = aG + (ks) * KSTEP;                             \
        const __half* sbp = bG + (ks) * KSTEP;                            \
        cp_async16(st, sa);                                               \
        cp_async16(st + sstep, sa + gstep);                               \
        cp_async16(st + TILE_BYTES, sbp);                                 \
        cp_async16(st + TILE_BYTES + sstep, sbp + gstep);                 \
    } while (0)

    // ---- prologue: fill 3 stages ----
    #pragma unroll
    for (int s = 0; s < STAGES; ++s) { ISSUE_STAGE(s, s); cp_commit(); }

    int buf = 0;
    for (int ks = 0; ks < ITERS; ++ks) {
        asm volatile("cp.async.wait_group %0;" :: "n"(STAGES - 1));
        __syncthreads();

        const uint32_t aBase = sb + buf * STAGE_BYTES + a_lane_off;
        const uint32_t bBase = sb + buf * STAGE_BYTES + TILE_BYTES + b_lane_off;
        #pragma unroll
        for (int kc = 0; kc < 4; ++kc) {
            uint32_t a[2][4], b[4][2];
            #pragma unroll
            for (int mt = 0; mt < 2; ++mt)
                ldsm4(a[mt], aBase + (uint32_t)mt * (16 * ROWB) + kc * 32);
            #pragma unroll
            for (int nt = 0; nt < 2; ++nt) {
                uint32_t t[4];
                ldsm4(t, bBase + (uint32_t)nt * (16 * ROWB) + kc * 32);
                b[2 * nt][0] = t[0]; b[2 * nt][1] = t[1];
                b[2 * nt + 1][0] = t[2]; b[2 * nt + 1][1] = t[3];
            }
            #pragma unroll
            for (int mt = 0; mt < 2; ++mt)
                #pragma unroll
                for (int n8 = 0; n8 < 4; ++n8)
                    mma16816(d[mt][n8], a[mt], b[n8]);
        }

        __syncthreads();
        if (ks + STAGES < ITERS) ISSUE_STAGE(ks + STAGES, buf);
        cp_commit();   // empty group in tail keeps wait_group arithmetic valid

        if (++buf == STAGES) buf = 0;
    }

    // ---- epilogue: registers -> gmem fp32 ----
    const int g = lid >> 2;
    const int tc = (lid & 3) * 2;
    #pragma unroll
    for (int mt = 0; mt < 2; ++mt) {
        const int row0 = mbase + m0w + mt * 16 + g;
        #pragma unroll
        for (int n8 = 0; n8 < 4; ++n8) {
            const int col = nbase + n0w + n8 * 8 + tc;
            float2 lo, hi;
            lo.x = d[mt][n8][0]; lo.y = d[mt][n8][1];
            hi.x = d[mt][n8][2]; hi.y = d[mt][n8][3];
            *reinterpret_cast<float2*>(out + (size_t)row0 * DIM_N + col) = lo;
            *reinterpret_cast<float2*>(out + (size_t)(row0 + 8) * DIM_N + col) = hi;
        }
    }
}

extern "C" void kernel_launch(void* const* d_in, const int* in_sizes, int n_in,
                              void* d_out, int out_size) {
    const float* x   = (const float*)d_in[0];
    const int*   w   = (const int*)d_in[1];
    const float* saz = (const float*)d_in[2];
    float* out = (float*)d_out;

    cudaFuncSetAttribute(gemm_kernel, cudaFuncAttributeMaxDynamicSharedMemorySize, SMEM_TOTAL);

    convert_x_kernel<<<(DIM_M * DIM_K / 8) / 256, 256>>>(x);
    dequant_w_kernel<<<((size_t)DIM_N * DIM_K / 8) / 256, 256>>>(w, saz);
    gemm_kernel<<<GRID_MT * GRID_NT, 512, SMEM_TOTAL>>>(out);
}